// round 11
// baseline (speedup 1.0000x reference)
#include <cuda_runtime.h>
#include <cuda_fp16.h>
#include <math.h>
#include <stdint.h>

#define NR 8192
#define DD 128
#define ALPHA 2.0f
#define EXPBIAS 96.0f

// ---------------- device globals ----------------
__device__ __align__(128) __half g_au_h[NR * DD];
__device__ __align__(128) __half g_tp_h[NR * DD];
__device__ float g_pos[NR];    // sum_{j!=i} exp(s_aa-B) + exp(s_tt-B)
__device__ float g_neg[NR];    // sum_{j!=i} exp(s_at-B)
__device__ double g_supcon;
__device__ double g_pt;
__device__ unsigned g_done;

// ---------------- convert (+zero) kernel: 4 elems/thread ----------------
__global__ void esup_split_kernel(const float* __restrict__ z_au,
                                  const float* __restrict__ z_tp) {
    const int t4 = blockIdx.x * blockDim.x + threadIdx.x;   // 0..262143
    const int base = t4 * 4;
    if (t4 < NR) { g_pos[t4] = 0.0f; g_neg[t4] = 0.0f; }
    if (t4 == 0) { g_supcon = 0.0; g_pt = 0.0; g_done = 0u; }

    const float4 a = *(const float4*)(z_au + base);
    const float4 b = *(const float4*)(z_tp + base);
    ((__half2*)(g_au_h + base))[0] = __floats2half2_rn(a.x, a.y);
    ((__half2*)(g_au_h + base))[1] = __floats2half2_rn(a.z, a.w);
    ((__half2*)(g_tp_h + base))[0] = __floats2half2_rn(b.x, b.y);
    ((__half2*)(g_tp_h + base))[1] = __floats2half2_rn(b.z, b.w);
}

// ---------------- PTX helpers (baseline ISA, compiles at compute_103) ----------------
__device__ __forceinline__ uint32_t smem_u32(const void* p) {
    uint32_t a;
    asm("{ .reg .u64 t; cvta.to.shared.u64 t, %1; cvt.u32.u64 %0, t; }" : "=r"(a) : "l"(p));
    return a;
}

#define CP_ASYNC16(dst_u32, src_ptr) \
    asm volatile("cp.async.cg.shared.global [%0], [%1], 16;" \
        :: "r"(dst_u32), "l"(src_ptr) : "memory")

// mbarrier (sm_80 baseline)
#define MBAR_INIT(addr, cnt) \
    asm volatile("mbarrier.init.shared.b64 [%0], %1;" :: "r"((uint32_t)(addr)), "r"((uint32_t)(cnt)) : "memory")
#define MBAR_ARRIVE(addr) \
    asm volatile("mbarrier.arrive.shared.b64 _, [%0];" :: "r"((uint32_t)(addr)) : "memory")
#define CP_ARRIVE_NOINC(addr) \
    asm volatile("cp.async.mbarrier.arrive.noinc.shared.b64 [%0];" :: "r"((uint32_t)(addr)) : "memory")
#define MBAR_WAIT(addr, par) do {                                                 \
    uint32_t _m = (uint32_t)(addr); uint32_t _p = (uint32_t)(par); uint32_t _d;   \
    asm volatile("{\n\t.reg .pred p;\n\t"                                         \
        "mbarrier.try_wait.parity.shared.b64 p, [%1], %2;\n\t"                    \
        "selp.b32 %0, 1, 0, p;\n\t}"                                              \
        : "=r"(_d) : "r"(_m), "r"(_p) : "memory");                                \
    if (!_d) {                                                                    \
        asm volatile("{\n\t.reg .pred P1;\n\t"                                    \
            "WL_%=:\n\t"                                                          \
            "mbarrier.try_wait.parity.shared.b64 P1, [%0], %1;\n\t"               \
            "@P1 bra.uni WD_%=;\n\t"                                              \
            "bra.uni WL_%=;\n\t"                                                  \
            "WD_%=:\n\t}" :: "r"(_m), "r"(_p) : "memory");                        \
    }                                                                             \
} while (0)

__device__ __forceinline__ void ldsm_x4(uint32_t* r, uint32_t addr) {
    asm volatile("ldmatrix.sync.aligned.m8n8.x4.shared.b16 {%0,%1,%2,%3}, [%4];"
        : "=r"(r[0]), "=r"(r[1]), "=r"(r[2]), "=r"(r[3]) : "r"(addr));
}

__device__ __forceinline__ void mma16816(float* c, const uint32_t* a,
                                         uint32_t b0, uint32_t b1) {
    asm volatile("mma.sync.aligned.m16n8k16.row.col.f32.f16.f16.f32 "
        "{%0,%1,%2,%3}, {%4,%5,%6,%7}, {%8,%9}, {%0,%1,%2,%3};"
        : "+f"(c[0]), "+f"(c[1]), "+f"(c[2]), "+f"(c[3])
        : "r"(a[0]), "r"(a[1]), "r"(a[2]), "r"(a[3]), "r"(b0), "r"(b1));
}

// exp(v - EXPBIAS) via single ex2.approx; 138.4987239... = 96 * log2(e)
__device__ __forceinline__ float fexp_b(float v) {
    float r;
    const float t = fmaf(v, 1.4426950408889634f, -138.4987239052529f);
    asm("ex2.approx.f32 %0, %1;" : "=f"(r) : "f"(t));
    return r;
}

// smem tile: [128 rows][16 chunks of 16B], chunk xor-swizzled by (row & 7)
__device__ __forceinline__ uint32_t tile_off(int row, int c) {
    return (uint32_t)(row * 256 + ((c ^ (row & 7)) << 4));
}

// ---------------- main fused GEMM + exp-sum kernel ----------------
// smem: A [0,32K); B stage s at 32K + s*32K (2 stages); scol [96K,100K); mbars.
#define SM_A    0u
#define SM_B    32768u
#define SM_COL  98304u
#define SM_MBAR 102400u     // full0, full1, empty0, empty1 (8B each)
#define SMEM_BYTES 102464

// grid layout: [0,288) job aa triangular, [288,576) job tt triangular,
// [576,1088) job at rectangular (64 row tiles x 8 chunks of 8 col tiles)
__global__ __launch_bounds__(256, 1) void esup_mma_kernel() {
    extern __shared__ char smem[];
    const uint32_t sb = smem_u32(smem);
    float* scol = (float*)(smem + SM_COL);       // [1024]
    const int tid = threadIdx.x;
    const int lane = tid & 31;
    const int wid = tid >> 5;
    const int wrow = wid & 3;        // 4 warp-rows of 32
    const int wcol = wid >> 2;       // 2 warp-cols of 64

    // ---- bid -> (job, row tile it, chunk of 8 col tiles) ----
    int job, it, chunk;
    {
        const int bid = blockIdx.x;
        if (bid < 576) {
            job = (bid < 288) ? 0 : 1;
            int s = (bid < 288) ? bid : bid - 288;
            int itv = 0;
            while (true) {
                const int w = 8 - (itv >> 3);
                if (s < w) break;
                s -= w; ++itv;
            }
            it = itv;
            chunk = (it >> 3) + s;
        } else {
            job = 2;
            const int r = bid - 576;
            it = r >> 3;
            chunk = r & 7;
        }
    }
    const int i0 = it * 128;
    const int j0base = chunk * 1024;

    const __half *Ahi_g, *Bhi_g;
    if (job == 0)      { Ahi_g = g_au_h; Bhi_g = g_au_h; }
    else if (job == 1) { Ahi_g = g_tp_h; Bhi_g = g_tp_h; }
    else               { Ahi_g = g_au_h; Bhi_g = g_tp_h; }

    // mbarrier init + scol zero
    if (tid == 0) {
        MBAR_INIT(sb + SM_MBAR + 0,  256);   // full0
        MBAR_INIT(sb + SM_MBAR + 8,  256);   // full1
        MBAR_INIT(sb + SM_MBAR + 16, 256);   // empty0
        MBAR_INIT(sb + SM_MBAR + 24, 256);   // empty1
    }
    if (job != 2) {
        #pragma unroll
        for (int q = 0; q < 4; ++q) scol[tid + q * 256] = 0.0f;
    }
    __syncthreads();

    // ---- prologue: A tile + B tile 0, arrive full0 on completion ----
    #pragma unroll
    for (int itr = 0; itr < 8; ++itr) {
        const int idx = tid + itr * 256;             // 0..2047
        const int row = idx >> 4, c = idx & 15;
        CP_ASYNC16(sb + SM_A + tile_off(row, c),
                   Ahi_g + (size_t)(i0 + row) * DD + c * 8);
    }
    #pragma unroll
    for (int itr = 0; itr < 8; ++itr) {
        const int idx = tid + itr * 256;
        const int row = idx >> 4, c = idx & 15;
        CP_ASYNC16(sb + SM_B + tile_off(row, c),
                   Bhi_g + (size_t)(j0base + row) * DD + c * 8);
    }
    CP_ARRIVE_NOINC(sb + SM_MBAR + 0);

    // persistent per-thread row exp-sums: [mt][rh]
    float rs[2][2] = {{0.f, 0.f}, {0.f, 0.f}};

    // hoisted fragment addressing bases
    const int arow0 = wrow * 32 + (lane & 15);
    const int bn0 = wcol * 64 + ((lane >> 4) << 3) + (lane & 7);

    // pipeline cursors
    int fs = 0, fp = 0;        // full: consumer, starts (0, ph0)
    int es = 1, ep = 1;        // empty: producer, starts (1, ph1) -> first wait passes

    for (int t = 0; t < 8; ++t) {
        // prefetch next B tile (per-thread, no CTA barrier)
        if (t < 7) {
            MBAR_WAIT(sb + SM_MBAR + 16 + es * 8, ep);
            const uint32_t stg = sb + SM_B + (uint32_t)es * 32768u;
            const int j0n = j0base + (t + 1) * 128;
            #pragma unroll
            for (int itr = 0; itr < 8; ++itr) {
                const int idx = tid + itr * 256;
                const int row = idx >> 4, c = idx & 15;
                CP_ASYNC16(stg + tile_off(row, c),
                           Bhi_g + (size_t)(j0n + row) * DD + c * 8);
            }
            CP_ARRIVE_NOINC(sb + SM_MBAR + es * 8);
            if (++es == 2) { es = 0; ep ^= 1; }
        }

        // wait current stage full
        MBAR_WAIT(sb + SM_MBAR + fs * 8, fp);
        if (++fs == 2) { fs = 0; fp ^= 1; }

        const uint32_t bsb = sb + SM_B + (uint32_t)(t & 1) * 32768u;
        const int j0 = j0base + t * 128;
        const int jt = chunk * 8 + t;

        float acc[2][8][4];
        #pragma unroll
        for (int mt = 0; mt < 2; ++mt)
            #pragma unroll
            for (int nt = 0; nt < 8; ++nt)
                #pragma unroll
                for (int q = 0; q < 4; ++q) acc[mt][nt][q] = 0.f;

        #pragma unroll
        for (int ks = 0; ks < 8; ++ks) {
            uint32_t Ah[2][4];
            const int ac = ks * 2 + (lane >> 4);
            #pragma unroll
            for (int mt = 0; mt < 2; ++mt)
                ldsm_x4(Ah[mt], sb + SM_A + tile_off(arow0 + mt * 16, ac));

            const int bc = ks * 2 + ((lane >> 3) & 1);
            #pragma unroll
            for (int nt2 = 0; nt2 < 4; ++nt2) {
                uint32_t Bh[4];                               // live briefly
                ldsm_x4(Bh, bsb + tile_off(bn0 + nt2 * 16, bc));
                #pragma unroll
                for (int mt = 0; mt < 2; ++mt) {
                    mma16816(acc[mt][nt2 * 2 + 0], Ah[mt], Bh[0], Bh[1]);
                    mma16816(acc[mt][nt2 * 2 + 1], Ah[mt], Bh[2], Bh[3]);
                }
            }
        }
        // stage consumed: free it for producers
        MBAR_ARRIVE(sb + SM_MBAR + 16 + (t & 1) * 8);

        // ---- epilogue (no CTA barrier — overlaps other warps' k-loops) ----
        if (job != 2 && jt > it) {
            // strictly upper triangular: row + column sums, no diag mask
            #pragma unroll
            for (int nt = 0; nt < 8; ++nt) {
                float c0 = 0.f, c1 = 0.f;
                #pragma unroll
                for (int mt = 0; mt < 2; ++mt) {
                    #pragma unroll
                    for (int rh = 0; rh < 2; ++rh) {
                        const float e0 = fexp_b(acc[mt][nt][rh * 2 + 0]);
                        const float e1 = fexp_b(acc[mt][nt][rh * 2 + 1]);
                        rs[mt][rh] += e0 + e1;
                        c0 += e0; c1 += e1;
                    }
                }
                // reduce over the 8 lanes sharing (lane & 3): bits 2..4
                c0 += __shfl_xor_sync(0xFFFFFFFF, c0, 4);
                c0 += __shfl_xor_sync(0xFFFFFFFF, c0, 8);
                c0 += __shfl_xor_sync(0xFFFFFFFF, c0, 16);
                c1 += __shfl_xor_sync(0xFFFFFFFF, c1, 4);
                c1 += __shfl_xor_sync(0xFFFFFFFF, c1, 8);
                c1 += __shfl_xor_sync(0xFFFFFFFF, c1, 16);
                if (lane < 4) {
                    const int lc = t * 128 + wcol * 64 + nt * 8 + lane * 2;
                    atomicAdd(&scol[lc], c0);
                    atomicAdd(&scol[lc + 1], c1);
                }
            }
        } else if (job == 2 || jt == it) {
            // row-only path (at job, or diagonal tiles of symmetric jobs)
            const bool dt = (jt == it);
            #pragma unroll
            for (int nt = 0; nt < 8; ++nt) {
                #pragma unroll
                for (int mt = 0; mt < 2; ++mt) {
                    #pragma unroll
                    for (int rh = 0; rh < 2; ++rh) {
                        float v0 = acc[mt][nt][rh * 2 + 0];
                        float v1 = acc[mt][nt][rh * 2 + 1];
                        if (dt) {
                            const int gr = i0 + wrow * 32 + mt * 16 + rh * 8 + (lane >> 2);
                            const int gc0 = j0 + wcol * 64 + nt * 8 + (lane & 3) * 2;
                            if (gr == gc0) v0 = -1e30f;
                            if (gr == gc0 + 1) v1 = -1e30f;
                        }
                        rs[mt][rh] += fexp_b(v0) + fexp_b(v1);
                    }
                }
            }
        }
        // jt < it on symmetric jobs: tile discarded (covered by transpose)
    }

    // ---- row flush: quad reduce + global atomics ----
    float* dst = (job == 2) ? g_neg : g_pos;
    #pragma unroll
    for (int mt = 0; mt < 2; ++mt) {
        #pragma unroll
        for (int rh = 0; rh < 2; ++rh) {
            float s = rs[mt][rh];
            s += __shfl_xor_sync(0xFFFFFFFF, s, 1);
            s += __shfl_xor_sync(0xFFFFFFFF, s, 2);
            if ((lane & 3) == 0) {
                const int gr = i0 + wrow * 32 + mt * 16 + rh * 8 + (lane >> 2);
                atomicAdd(dst + gr, s);
            }
        }
    }

    // ---- column flush (symmetric jobs: transpose contribution) ----
    if (job != 2) {
        __syncthreads();
        #pragma unroll
        for (int q = 0; q < 4; ++q) {
            const int idx = tid + q * 256;
            const float v = scol[idx];
            if (v != 0.0f) atomicAdd(&g_pos[j0base + idx], v);
        }
    }
}

// ---------------- per-row reduction (+ fused finalize) ----------------
__global__ void esup_rowreduce_kernel(const float* __restrict__ z_au,
                                      const float* __restrict__ z_tp,
                                      const float* __restrict__ fc,
                                      float* __restrict__ out) {
    __shared__ float sv[8], sp[8];
    const int lane = threadIdx.x & 31;
    const int wid = threadIdx.x >> 5;
    const int row = blockIdx.x * 8 + wid;

    const float4 a = *(const float4*)(z_au + (size_t)row * DD + lane * 4);
    const float4 b = *(const float4*)(z_tp + (size_t)row * DD + lane * 4);
    const float4 w0 = *(const float4*)(fc + lane * 4);
    const float4 w1 = *(const float4*)(fc + DD + lane * 4);

    float diag = a.x * b.x + a.y * b.y + a.z * b.z + a.w * b.w;
    float pt = (a.x - b.x) * (w1.x - w0.x) + (a.y - b.y) * (w1.y - w0.y) +
               (a.z - b.z) * (w1.z - w0.z) + (a.w - b.w) * (w1.w - w0.w);
    #pragma unroll
    for (int s = 16; s > 0; s >>= 1) {
        diag += __shfl_xor_sync(0xFFFFFFFF, diag, s);
        pt   += __shfl_xor_sync(0xFFFFFFFF, pt, s);
    }
    if (lane == 0) {
        const float pos = EXPBIAS + logf(g_pos[row]);
        const float neg = EXPBIAS + logf(g_neg[row]);
        sv[wid] = -pos + neg + ALPHA * diag;
        sp[wid] = pt;
    }
    __syncthreads();
    if (threadIdx.x == 0) {
        double s = 0.0, p = 0.0;
        #pragma unroll
        for (int i = 0; i < 8; ++i) { s += (double)sv[i]; p += (double)sp[i]; }
        atomicAdd(&g_supcon, s);
        atomicAdd(&g_pt, p);
        __threadfence();
        const unsigned prev = atomicAdd(&g_done, 1u);
        if (prev == gridDim.x - 1) {
            const double st = atomicAdd(&g_supcon, 0.0);
            const double pp = atomicAdd(&g_pt, 0.0);
            out[0] = (float)((pp / (double)NR + st) / (double)(NR + 2));
        }
    }
}

// ---------------- launch ----------------
extern "C" void kernel_launch(void* const* d_in, const int* in_sizes, int n_in,
                              void* d_out, int out_size) {
    const float* z_au = (const float*)d_in[0];
    const float* z_tp = (const float*)d_in[1];
    const float* fc   = (const float*)d_in[2];
    float* out = (float*)d_out;

    cudaFuncSetAttribute(esup_mma_kernel,
                         cudaFuncAttributeMaxDynamicSharedMemorySize, SMEM_BYTES);

    esup_split_kernel<<<(NR * DD / 4) / 256, 256>>>(z_au, z_tp);
    esup_mma_kernel<<<1088, 256, SMEM_BYTES>>>();
    esup_rowreduce_kernel<<<NR / 8, 256>>>(z_au, z_tp, fc, out);
}

// round 12
// speedup vs baseline: 1.2821x; 1.2821x over previous
#include <cuda_runtime.h>
#include <cuda_fp16.h>
#include <math.h>
#include <stdint.h>

#define NR 8192
#define DD 128
#define ALPHA 2.0f
#define EXPBIAS 96.0f

// ---------------- device globals ----------------
__device__ __align__(128) __half g_au_h[NR * DD];
__device__ __align__(128) __half g_tp_h[NR * DD];
__device__ float g_pos[NR];    // sum_{j!=i} exp(s_aa-B) + exp(s_tt-B)
__device__ float g_neg[NR];    // sum_{j!=i} exp(s_at-B)
__device__ double g_supcon;
__device__ double g_pt;
__device__ unsigned g_done;

// ---------------- convert (+zero) kernel: 4 elems/thread ----------------
__global__ void esup_split_kernel(const float* __restrict__ z_au,
                                  const float* __restrict__ z_tp) {
    const int t4 = blockIdx.x * blockDim.x + threadIdx.x;   // 0..262143
    const int base = t4 * 4;
    if (t4 < NR) { g_pos[t4] = 0.0f; g_neg[t4] = 0.0f; }
    if (t4 == 0) { g_supcon = 0.0; g_pt = 0.0; g_done = 0u; }

    const float4 a = *(const float4*)(z_au + base);
    const float4 b = *(const float4*)(z_tp + base);
    ((__half2*)(g_au_h + base))[0] = __floats2half2_rn(a.x, a.y);
    ((__half2*)(g_au_h + base))[1] = __floats2half2_rn(a.z, a.w);
    ((__half2*)(g_tp_h + base))[0] = __floats2half2_rn(b.x, b.y);
    ((__half2*)(g_tp_h + base))[1] = __floats2half2_rn(b.z, b.w);
}

// ---------------- PTX helpers (baseline ISA, compiles at compute_103) ----------------
__device__ __forceinline__ uint32_t smem_u32(const void* p) {
    uint32_t a;
    asm("{ .reg .u64 t; cvta.to.shared.u64 t, %1; cvt.u32.u64 %0, t; }" : "=r"(a) : "l"(p));
    return a;
}

#define CP_ASYNC16(dst_u32, src_ptr) \
    asm volatile("cp.async.cg.shared.global [%0], [%1], 16;" \
        :: "r"(dst_u32), "l"(src_ptr) : "memory")

// mbarrier (sm_80 baseline)
#define MBAR_INIT(addr, cnt) \
    asm volatile("mbarrier.init.shared.b64 [%0], %1;" :: "r"((uint32_t)(addr)), "r"((uint32_t)(cnt)) : "memory")
#define MBAR_ARRIVE(addr) \
    asm volatile("mbarrier.arrive.shared.b64 _, [%0];" :: "r"((uint32_t)(addr)) : "memory")
#define CP_ARRIVE_NOINC(addr) \
    asm volatile("cp.async.mbarrier.arrive.noinc.shared.b64 [%0];" :: "r"((uint32_t)(addr)) : "memory")
#define MBAR_WAIT(addr, par) do {                                                 \
    uint32_t _m = (uint32_t)(addr); uint32_t _p = (uint32_t)(par); uint32_t _d;   \
    asm volatile("{\n\t.reg .pred p;\n\t"                                         \
        "mbarrier.try_wait.parity.shared.b64 p, [%1], %2;\n\t"                    \
        "selp.b32 %0, 1, 0, p;\n\t}"                                              \
        : "=r"(_d) : "r"(_m), "r"(_p) : "memory");                                \
    if (!_d) {                                                                    \
        asm volatile("{\n\t.reg .pred P1;\n\t"                                    \
            "WL_%=:\n\t"                                                          \
            "mbarrier.try_wait.parity.shared.b64 P1, [%0], %1;\n\t"               \
            "@P1 bra.uni WD_%=;\n\t"                                              \
            "bra.uni WL_%=;\n\t"                                                  \
            "WD_%=:\n\t}" :: "r"(_m), "r"(_p) : "memory");                        \
    }                                                                             \
} while (0)

__device__ __forceinline__ void ldsm_x4(uint32_t* r, uint32_t addr) {
    asm volatile("ldmatrix.sync.aligned.m8n8.x4.shared.b16 {%0,%1,%2,%3}, [%4];"
        : "=r"(r[0]), "=r"(r[1]), "=r"(r[2]), "=r"(r[3]) : "r"(addr));
}

__device__ __forceinline__ void mma16816(float* c, const uint32_t* a,
                                         uint32_t b0, uint32_t b1) {
    asm volatile("mma.sync.aligned.m16n8k16.row.col.f32.f16.f16.f32 "
        "{%0,%1,%2,%3}, {%4,%5,%6,%7}, {%8,%9}, {%0,%1,%2,%3};"
        : "+f"(c[0]), "+f"(c[1]), "+f"(c[2]), "+f"(c[3])
        : "r"(a[0]), "r"(a[1]), "r"(a[2]), "r"(a[3]), "r"(b0), "r"(b1));
}

// exp(v - EXPBIAS) via single ex2.approx; 138.4987239... = 96 * log2(e)
__device__ __forceinline__ float fexp_b(float v) {
    float r;
    const float t = fmaf(v, 1.4426950408889634f, -138.4987239052529f);
    asm("ex2.approx.f32 %0, %1;" : "=f"(r) : "f"(t));
    return r;
}

// smem tile: [128 rows][16 chunks of 16B], chunk xor-swizzled by (row & 7)
__device__ __forceinline__ uint32_t tile_off(int row, int c) {
    return (uint32_t)(row * 256 + ((c ^ (row & 7)) << 4));
}

// ---------------- main fused GEMM + exp-sum kernel ----------------
// smem: A [0,32K); B stage s at 32K + s*32K (2 stages); scol [96K,100K); mbars.
#define SM_A    0u
#define SM_B    32768u
#define SM_COL  98304u
#define SM_MBAR 102400u     // full0, full1, empty0, empty1 (8B each)
#define SMEM_BYTES 102464

// grid layout: [0,288) job aa triangular, [288,576) job tt triangular,
// [576,1088) job at rectangular (64 row tiles x 8 chunks of 8 col tiles)
__global__ __launch_bounds__(256, 2) void esup_mma_kernel() {
    extern __shared__ char smem[];
    const uint32_t sb = smem_u32(smem);
    float* scol = (float*)(smem + SM_COL);       // [1024]
    const int tid = threadIdx.x;
    const int lane = tid & 31;
    const int wid = tid >> 5;
    const int wrow = wid & 3;        // 4 warp-rows of 32
    const int wcol = wid >> 2;       // 2 warp-cols of 64

    // ---- bid -> (job, row tile it, chunk of 8 col tiles) ----
    int job, it, chunk;
    {
        const int bid = blockIdx.x;
        if (bid < 576) {
            job = (bid < 288) ? 0 : 1;
            int s = (bid < 288) ? bid : bid - 288;
            int itv = 0;
            while (true) {
                const int w = 8 - (itv >> 3);
                if (s < w) break;
                s -= w; ++itv;
            }
            it = itv;
            chunk = (it >> 3) + s;
        } else {
            job = 2;
            const int r = bid - 576;
            it = r >> 3;
            chunk = r & 7;
        }
    }
    const int i0 = it * 128;
    const int j0base = chunk * 1024;

    const __half *Ahi_g, *Bhi_g;
    if (job == 0)      { Ahi_g = g_au_h; Bhi_g = g_au_h; }
    else if (job == 1) { Ahi_g = g_tp_h; Bhi_g = g_tp_h; }
    else               { Ahi_g = g_au_h; Bhi_g = g_tp_h; }

    // mbarrier init + scol zero
    if (tid == 0) {
        MBAR_INIT(sb + SM_MBAR + 0,  256);   // full0
        MBAR_INIT(sb + SM_MBAR + 8,  256);   // full1
        MBAR_INIT(sb + SM_MBAR + 16, 256);   // empty0
        MBAR_INIT(sb + SM_MBAR + 24, 256);   // empty1
    }
    if (job != 2) {
        #pragma unroll
        for (int q = 0; q < 4; ++q) scol[tid + q * 256] = 0.0f;
    }
    __syncthreads();

    // ---- prologue: A tile + B tile 0, arrive full0 on completion ----
    #pragma unroll
    for (int itr = 0; itr < 8; ++itr) {
        const int idx = tid + itr * 256;             // 0..2047
        const int row = idx >> 4, c = idx & 15;
        CP_ASYNC16(sb + SM_A + tile_off(row, c),
                   Ahi_g + (size_t)(i0 + row) * DD + c * 8);
    }
    #pragma unroll
    for (int itr = 0; itr < 8; ++itr) {
        const int idx = tid + itr * 256;
        const int row = idx >> 4, c = idx & 15;
        CP_ASYNC16(sb + SM_B + tile_off(row, c),
                   Bhi_g + (size_t)(j0base + row) * DD + c * 8);
    }
    CP_ARRIVE_NOINC(sb + SM_MBAR + 0);

    // persistent per-thread row exp-sums: [mt][rh]
    float rs[2][2] = {{0.f, 0.f}, {0.f, 0.f}};

    // hoisted fragment addressing bases
    const int arow0 = wrow * 32 + (lane & 15);
    const int bn0 = wcol * 64 + ((lane >> 4) << 3) + (lane & 7);

    // pipeline cursors
    int fs = 0, fp = 0;        // full: consumer, starts (0, ph0)
    int es = 1, ep = 1;        // empty: producer, starts (1, ph1) -> first wait passes

    for (int t = 0; t < 8; ++t) {
        // prefetch next B tile (per-thread, no CTA barrier)
        if (t < 7) {
            MBAR_WAIT(sb + SM_MBAR + 16 + es * 8, ep);
            const uint32_t stg = sb + SM_B + (uint32_t)es * 32768u;
            const int j0n = j0base + (t + 1) * 128;
            #pragma unroll
            for (int itr = 0; itr < 8; ++itr) {
                const int idx = tid + itr * 256;
                const int row = idx >> 4, c = idx & 15;
                CP_ASYNC16(stg + tile_off(row, c),
                           Bhi_g + (size_t)(j0n + row) * DD + c * 8);
            }
            CP_ARRIVE_NOINC(sb + SM_MBAR + es * 8);
            if (++es == 2) { es = 0; ep ^= 1; }
        }

        // wait current stage full (must precede empty-arrive even when skipping,
        // so a recycled stage never has two generations of cp.async in flight)
        MBAR_WAIT(sb + SM_MBAR + fs * 8, fp);
        if (++fs == 2) { fs = 0; fp ^= 1; }

        const int jt = chunk * 8 + t;
        const bool live = (job == 2) || (jt >= it);

        if (live) {
            const uint32_t bsb = sb + SM_B + (uint32_t)(t & 1) * 32768u;
            const int j0 = j0base + t * 128;

            float acc[2][8][4];
            #pragma unroll
            for (int mt = 0; mt < 2; ++mt)
                #pragma unroll
                for (int nt = 0; nt < 8; ++nt)
                    #pragma unroll
                    for (int q = 0; q < 4; ++q) acc[mt][nt][q] = 0.f;

            #pragma unroll
            for (int ks = 0; ks < 8; ++ks) {
                uint32_t Ah[2][4];
                const int ac = ks * 2 + (lane >> 4);
                #pragma unroll
                for (int mt = 0; mt < 2; ++mt)
                    ldsm_x4(Ah[mt], sb + SM_A + tile_off(arow0 + mt * 16, ac));

                const int bc = ks * 2 + ((lane >> 3) & 1);
                #pragma unroll
                for (int nt2 = 0; nt2 < 4; ++nt2) {
                    uint32_t Bh[4];                               // live briefly
                    ldsm_x4(Bh, bsb + tile_off(bn0 + nt2 * 16, bc));
                    #pragma unroll
                    for (int mt = 0; mt < 2; ++mt) {
                        mma16816(acc[mt][nt2 * 2 + 0], Ah[mt], Bh[0], Bh[1]);
                        mma16816(acc[mt][nt2 * 2 + 1], Ah[mt], Bh[2], Bh[3]);
                    }
                }
            }
            // stage consumed: free it for producers
            MBAR_ARRIVE(sb + SM_MBAR + 16 + (t & 1) * 8);

            // ---- epilogue (no CTA barrier — overlaps other warps' k-loops) ----
            if (job != 2 && jt > it) {
                // strictly upper triangular: row + column sums, no diag mask
                #pragma unroll
                for (int nt = 0; nt < 8; ++nt) {
                    float c0 = 0.f, c1 = 0.f;
                    #pragma unroll
                    for (int mt = 0; mt < 2; ++mt) {
                        #pragma unroll
                        for (int rh = 0; rh < 2; ++rh) {
                            const float e0 = fexp_b(acc[mt][nt][rh * 2 + 0]);
                            const float e1 = fexp_b(acc[mt][nt][rh * 2 + 1]);
                            rs[mt][rh] += e0 + e1;
                            c0 += e0; c1 += e1;
                        }
                    }
                    // reduce over the 8 lanes sharing (lane & 3): bits 2..4
                    c0 += __shfl_xor_sync(0xFFFFFFFF, c0, 4);
                    c0 += __shfl_xor_sync(0xFFFFFFFF, c0, 8);
                    c0 += __shfl_xor_sync(0xFFFFFFFF, c0, 16);
                    c1 += __shfl_xor_sync(0xFFFFFFFF, c1, 4);
                    c1 += __shfl_xor_sync(0xFFFFFFFF, c1, 8);
                    c1 += __shfl_xor_sync(0xFFFFFFFF, c1, 16);
                    if (lane < 4) {
                        const int lc = t * 128 + wcol * 64 + nt * 8 + lane * 2;
                        atomicAdd(&scol[lc], c0);
                        atomicAdd(&scol[lc + 1], c1);
                    }
                }
            } else {
                // row-only path (at job, or diagonal tiles of symmetric jobs)
                const bool dt = (jt == it);
                #pragma unroll
                for (int nt = 0; nt < 8; ++nt) {
                    #pragma unroll
                    for (int mt = 0; mt < 2; ++mt) {
                        #pragma unroll
                        for (int rh = 0; rh < 2; ++rh) {
                            float v0 = acc[mt][nt][rh * 2 + 0];
                            float v1 = acc[mt][nt][rh * 2 + 1];
                            if (dt) {
                                const int gr = i0 + wrow * 32 + mt * 16 + rh * 8 + (lane >> 2);
                                const int gc0 = j0 + wcol * 64 + nt * 8 + (lane & 3) * 2;
                                if (gr == gc0) v0 = -1e30f;
                                if (gr == gc0 + 1) v1 = -1e30f;
                            }
                            rs[mt][rh] += fexp_b(v0) + fexp_b(v1);
                        }
                    }
                }
            }
        } else {
            // discarded tile (jt < it on symmetric jobs): no compute,
            // but still recycle the stage for the producer side.
            MBAR_ARRIVE(sb + SM_MBAR + 16 + (t & 1) * 8);
        }
    }

    // ---- row flush: quad reduce + global atomics ----
    float* dst = (job == 2) ? g_neg : g_pos;
    #pragma unroll
    for (int mt = 0; mt < 2; ++mt) {
        #pragma unroll
        for (int rh = 0; rh < 2; ++rh) {
            float s = rs[mt][rh];
            s += __shfl_xor_sync(0xFFFFFFFF, s, 1);
            s += __shfl_xor_sync(0xFFFFFFFF, s, 2);
            if ((lane & 3) == 0) {
                const int gr = i0 + wrow * 32 + mt * 16 + rh * 8 + (lane >> 2);
                atomicAdd(dst + gr, s);
            }
        }
    }

    // ---- column flush (symmetric jobs: transpose contribution) ----
    if (job != 2) {
        __syncthreads();
        #pragma unroll
        for (int q = 0; q < 4; ++q) {
            const int idx = tid + q * 256;
            const float v = scol[idx];
            if (v != 0.0f) atomicAdd(&g_pos[j0base + idx], v);
        }
    }
}

// ---------------- per-row reduction (+ fused finalize) ----------------
__global__ void esup_rowreduce_kernel(const float* __restrict__ z_au,
                                      const float* __restrict__ z_tp,
                                      const float* __restrict__ fc,
                                      float* __restrict__ out) {
    __shared__ float sv[8], sp[8];
    const int lane = threadIdx.x & 31;
    const int wid = threadIdx.x >> 5;
    const int row = blockIdx.x * 8 + wid;

    const float4 a = *(const float4*)(z_au + (size_t)row * DD + lane * 4);
    const float4 b = *(const float4*)(z_tp + (size_t)row * DD + lane * 4);
    const float4 w0 = *(const float4*)(fc + lane * 4);
    const float4 w1 = *(const float4*)(fc + DD + lane * 4);

    float diag = a.x * b.x + a.y * b.y + a.z * b.z + a.w * b.w;
    float pt = (a.x - b.x) * (w1.x - w0.x) + (a.y - b.y) * (w1.y - w0.y) +
               (a.z - b.z) * (w1.z - w0.z) + (a.w - b.w) * (w1.w - w0.w);
    #pragma unroll
    for (int s = 16; s > 0; s >>= 1) {
        diag += __shfl_xor_sync(0xFFFFFFFF, diag, s);
        pt   += __shfl_xor_sync(0xFFFFFFFF, pt, s);
    }
    if (lane == 0) {
        const float pos = EXPBIAS + logf(g_pos[row]);
        const float neg = EXPBIAS + logf(g_neg[row]);
        sv[wid] = -pos + neg + ALPHA * diag;
        sp[wid] = pt;
    }
    __syncthreads();
    if (threadIdx.x == 0) {
        double s = 0.0, p = 0.0;
        #pragma unroll
        for (int i = 0; i < 8; ++i) { s += (double)sv[i]; p += (double)sp[i]; }
        atomicAdd(&g_supcon, s);
        atomicAdd(&g_pt, p);
        __threadfence();
        const unsigned prev = atomicAdd(&g_done, 1u);
        if (prev == gridDim.x - 1) {
            const double st = atomicAdd(&g_supcon, 0.0);
            const double pp = atomicAdd(&g_pt, 0.0);
            out[0] = (float)((pp / (double)NR + st) / (double)(NR + 2));
        }
    }
}

// ---------------- launch ----------------
extern "C" void kernel_launch(void* const* d_in, const int* in_sizes, int n_in,
                              void* d_out, int out_size) {
    const float* z_au = (const float*)d_in[0];
    const float* z_tp = (const float*)d_in[1];
    const float* fc   = (const float*)d_in[2];
    float* out = (float*)d_out;

    cudaFuncSetAttribute(esup_mma_kernel,
                         cudaFuncAttributeMaxDynamicSharedMemorySize, SMEM_BYTES);

    esup_split_kernel<<<(NR * DD / 4) / 256, 256>>>(z_au, z_tp);
    esup_mma_kernel<<<1088, 256, SMEM_BYTES>>>();
    esup_rowreduce_kernel<<<NR / 8, 256>>>(z_au, z_tp, fc, out);
}

// round 13
// speedup vs baseline: 1.2895x; 1.0058x over previous
#include <cuda_runtime.h>
#include <cuda_fp16.h>
#include <math.h>
#include <stdint.h>

#define NR 8192
#define DD 128
#define ALPHA 2.0f
#define EXPBIAS 96.0f

// ---------------- device globals ----------------
__device__ __align__(128) __half g_au_h[NR * DD];
__device__ __align__(128) __half g_tp_h[NR * DD];
__device__ float g_pos[NR];    // sum_{j!=i} exp(s_aa-B) + exp(s_tt-B)
__device__ float g_neg[NR];    // sum_{j!=i} exp(s_at-B)
__device__ double g_supcon;
__device__ double g_pt;
__device__ unsigned g_done;

// ---------------- convert (+zero) kernel: 4 elems/thread ----------------
__global__ void esup_split_kernel(const float* __restrict__ z_au,
                                  const float* __restrict__ z_tp) {
    const int t4 = blockIdx.x * blockDim.x + threadIdx.x;   // 0..262143
    const int base = t4 * 4;
    if (t4 < NR) { g_pos[t4] = 0.0f; g_neg[t4] = 0.0f; }
    if (t4 == 0) { g_supcon = 0.0; g_pt = 0.0; g_done = 0u; }

    const float4 a = *(const float4*)(z_au + base);
    const float4 b = *(const float4*)(z_tp + base);
    ((__half2*)(g_au_h + base))[0] = __floats2half2_rn(a.x, a.y);
    ((__half2*)(g_au_h + base))[1] = __floats2half2_rn(a.z, a.w);
    ((__half2*)(g_tp_h + base))[0] = __floats2half2_rn(b.x, b.y);
    ((__half2*)(g_tp_h + base))[1] = __floats2half2_rn(b.z, b.w);
}

// ---------------- PTX helpers (baseline ISA, compiles at compute_103) ----------------
__device__ __forceinline__ uint32_t smem_u32(const void* p) {
    uint32_t a;
    asm("{ .reg .u64 t; cvta.to.shared.u64 t, %1; cvt.u32.u64 %0, t; }" : "=r"(a) : "l"(p));
    return a;
}

#define CP_ASYNC16(dst_u32, src_ptr) \
    asm volatile("cp.async.cg.shared.global [%0], [%1], 16;" \
        :: "r"(dst_u32), "l"(src_ptr) : "memory")

// mbarrier (sm_80 baseline)
#define MBAR_INIT(addr, cnt) \
    asm volatile("mbarrier.init.shared.b64 [%0], %1;" :: "r"((uint32_t)(addr)), "r"((uint32_t)(cnt)) : "memory")
#define MBAR_ARRIVE(addr) \
    asm volatile("mbarrier.arrive.shared.b64 _, [%0];" :: "r"((uint32_t)(addr)) : "memory")
#define CP_ARRIVE_NOINC(addr) \
    asm volatile("cp.async.mbarrier.arrive.noinc.shared.b64 [%0];" :: "r"((uint32_t)(addr)) : "memory")
#define MBAR_WAIT(addr, par) do {                                                 \
    uint32_t _m = (uint32_t)(addr); uint32_t _p = (uint32_t)(par); uint32_t _d;   \
    asm volatile("{\n\t.reg .pred p;\n\t"                                         \
        "mbarrier.try_wait.parity.shared.b64 p, [%1], %2;\n\t"                    \
        "selp.b32 %0, 1, 0, p;\n\t}"                                              \
        : "=r"(_d) : "r"(_m), "r"(_p) : "memory");                                \
    if (!_d) {                                                                    \
        asm volatile("{\n\t.reg .pred P1;\n\t"                                    \
            "WL_%=:\n\t"                                                          \
            "mbarrier.try_wait.parity.shared.b64 P1, [%0], %1;\n\t"               \
            "@P1 bra.uni WD_%=;\n\t"                                              \
            "bra.uni WL_%=;\n\t"                                                  \
            "WD_%=:\n\t}" :: "r"(_m), "r"(_p) : "memory");                        \
    }                                                                             \
} while (0)

__device__ __forceinline__ void ldsm_x4(uint32_t* r, uint32_t addr) {
    asm volatile("ldmatrix.sync.aligned.m8n8.x4.shared.b16 {%0,%1,%2,%3}, [%4];"
        : "=r"(r[0]), "=r"(r[1]), "=r"(r[2]), "=r"(r[3]) : "r"(addr));
}

__device__ __forceinline__ void mma16816(float* c, const uint32_t* a,
                                         uint32_t b0, uint32_t b1) {
    asm volatile("mma.sync.aligned.m16n8k16.row.col.f32.f16.f16.f32 "
        "{%0,%1,%2,%3}, {%4,%5,%6,%7}, {%8,%9}, {%0,%1,%2,%3};"
        : "+f"(c[0]), "+f"(c[1]), "+f"(c[2]), "+f"(c[3])
        : "r"(a[0]), "r"(a[1]), "r"(a[2]), "r"(a[3]), "r"(b0), "r"(b1));
}

// exp(v - EXPBIAS) via single ex2.approx; 138.4987239... = 96 * log2(e)
__device__ __forceinline__ float fexp_b(float v) {
    float r;
    const float t = fmaf(v, 1.4426950408889634f, -138.4987239052529f);
    asm("ex2.approx.f32 %0, %1;" : "=f"(r) : "f"(t));
    return r;
}

// smem tile: [128 rows][16 chunks of 16B], chunk xor-swizzled by (row & 7)
__device__ __forceinline__ uint32_t tile_off(int row, int c) {
    return (uint32_t)(row * 256 + ((c ^ (row & 7)) << 4));
}

// ---------------- main fused GEMM + exp-sum kernel ----------------
// smem: A [0,32K); B stage s at 32K + s*32K (2 stages); scol [96K,100K); mbars.
#define SM_A    0u
#define SM_B    32768u
#define SM_COL  98304u
#define SM_MBAR 102400u     // full0, full1, empty0, empty1 (8B each)
#define SMEM_BYTES 102464

// grid layout: [0,288) job aa triangular, [288,576) job tt triangular,
// [576,1088) job at rectangular (64 row tiles x 8 chunks of 8 col tiles)
__global__ __launch_bounds__(256, 2) void esup_mma_kernel() {
    extern __shared__ char smem[];
    const uint32_t sb = smem_u32(smem);
    float* scol = (float*)(smem + SM_COL);       // [1024]
    const int tid = threadIdx.x;
    const int lane = tid & 31;
    const int wid = tid >> 5;
    const int wrow = wid & 3;        // 4 warp-rows of 32
    const int wcol = wid >> 2;       // 2 warp-cols of 64

    // ---- bid -> (job, row tile it, chunk of 8 col tiles) ----
    int job, it, chunk;
    {
        const int bid = blockIdx.x;
        if (bid < 576) {
            job = (bid < 288) ? 0 : 1;
            int s = (bid < 288) ? bid : bid - 288;
            int itv = 0;
            while (true) {
                const int w = 8 - (itv >> 3);
                if (s < w) break;
                s -= w; ++itv;
            }
            it = itv;
            chunk = (it >> 3) + s;
        } else {
            job = 2;
            const int r = bid - 576;
            it = r >> 3;
            chunk = r & 7;
        }
    }
    const int i0 = it * 128;
    const int j0base = chunk * 1024;

    const __half *Ahi_g, *Bhi_g;
    if (job == 0)      { Ahi_g = g_au_h; Bhi_g = g_au_h; }
    else if (job == 1) { Ahi_g = g_tp_h; Bhi_g = g_tp_h; }
    else               { Ahi_g = g_au_h; Bhi_g = g_tp_h; }

    // mbarrier init + scol zero
    if (tid == 0) {
        MBAR_INIT(sb + SM_MBAR + 0,  256);   // full0
        MBAR_INIT(sb + SM_MBAR + 8,  256);   // full1
        MBAR_INIT(sb + SM_MBAR + 16, 256);   // empty0
        MBAR_INIT(sb + SM_MBAR + 24, 256);   // empty1
    }
    if (job != 2) {
        #pragma unroll
        for (int q = 0; q < 4; ++q) scol[tid + q * 256] = 0.0f;
    }
    __syncthreads();

    // ---- prologue: A tile + B tile 0, arrive full0 on completion ----
    #pragma unroll
    for (int itr = 0; itr < 8; ++itr) {
        const int idx = tid + itr * 256;             // 0..2047
        const int row = idx >> 4, c = idx & 15;
        CP_ASYNC16(sb + SM_A + tile_off(row, c),
                   Ahi_g + (size_t)(i0 + row) * DD + c * 8);
    }
    #pragma unroll
    for (int itr = 0; itr < 8; ++itr) {
        const int idx = tid + itr * 256;
        const int row = idx >> 4, c = idx & 15;
        CP_ASYNC16(sb + SM_B + tile_off(row, c),
                   Bhi_g + (size_t)(j0base + row) * DD + c * 8);
    }
    CP_ARRIVE_NOINC(sb + SM_MBAR + 0);

    // persistent per-thread row exp-sums: [mt][rh]
    float rs[2][2] = {{0.f, 0.f}, {0.f, 0.f}};

    // hoisted fragment addressing bases
    const int arow0 = wrow * 32 + (lane & 15);
    const int bn0 = wcol * 64 + ((lane >> 4) << 3) + (lane & 7);
    const int acoff = (lane >> 4);            // A chunk parity
    const int bcoff = ((lane >> 3) & 1);      // B chunk parity

    // pipeline cursors
    int fs = 0, fp = 0;        // full: consumer, starts (0, ph0)
    int es = 1, ep = 1;        // empty: producer, starts (1, ph1) -> first wait passes

    for (int t = 0; t < 8; ++t) {
        // prefetch next B tile (per-thread, no CTA barrier)
        if (t < 7) {
            MBAR_WAIT(sb + SM_MBAR + 16 + es * 8, ep);
            const uint32_t stg = sb + SM_B + (uint32_t)es * 32768u;
            const int j0n = j0base + (t + 1) * 128;
            #pragma unroll
            for (int itr = 0; itr < 8; ++itr) {
                const int idx = tid + itr * 256;
                const int row = idx >> 4, c = idx & 15;
                CP_ASYNC16(stg + tile_off(row, c),
                           Bhi_g + (size_t)(j0n + row) * DD + c * 8);
            }
            CP_ARRIVE_NOINC(sb + SM_MBAR + es * 8);
            if (++es == 2) { es = 0; ep ^= 1; }
        }

        // wait current stage full (must precede empty-arrive even when skipping,
        // so a recycled stage never has two generations of cp.async in flight)
        MBAR_WAIT(sb + SM_MBAR + fs * 8, fp);
        if (++fs == 2) { fs = 0; fp ^= 1; }

        const int jt = chunk * 8 + t;
        const bool live = (job == 2) || (jt >= it);

        if (live) {
            const uint32_t bsb = sb + SM_B + (uint32_t)(t & 1) * 32768u;
            const int j0 = j0base + t * 128;

            float acc[2][8][4];
            #pragma unroll
            for (int mt = 0; mt < 2; ++mt)
                #pragma unroll
                for (int nt = 0; nt < 8; ++nt)
                    #pragma unroll
                    for (int q = 0; q < 4; ++q) acc[mt][nt][q] = 0.f;

            // ---- software-pipelined k-loop: double-buffered fragments ----
            uint32_t Ah[2][2][4];    // [buf][mt][4]
            uint32_t Bh[2][4];       // [buf][4]
            ldsm_x4(Ah[0][0], sb + SM_A + tile_off(arow0,      acoff));
            ldsm_x4(Ah[0][1], sb + SM_A + tile_off(arow0 + 16, acoff));
            ldsm_x4(Bh[0],    bsb + tile_off(bn0, bcoff));

            #pragma unroll
            for (int step = 0; step < 32; ++step) {
                const int ks  = step >> 2;
                const int nt2 = step & 3;
                const int ab  = ks & 1;
                const int bb  = step & 1;
                // prefetch next B fragment
                if (step < 31) {
                    const int ns  = step + 1;
                    const int nbc = (ns >> 2) * 2 + bcoff;
                    ldsm_x4(Bh[bb ^ 1], bsb + tile_off(bn0 + (ns & 3) * 16, nbc));
                }
                // prefetch next A fragments at start of each ks group
                if (nt2 == 0 && ks < 7) {
                    const int nac = (ks + 1) * 2 + acoff;
                    ldsm_x4(Ah[ab ^ 1][0], sb + SM_A + tile_off(arow0,      nac));
                    ldsm_x4(Ah[ab ^ 1][1], sb + SM_A + tile_off(arow0 + 16, nac));
                }
                // consume current fragments
                mma16816(acc[0][nt2 * 2 + 0], Ah[ab][0], Bh[bb][0], Bh[bb][1]);
                mma16816(acc[0][nt2 * 2 + 1], Ah[ab][0], Bh[bb][2], Bh[bb][3]);
                mma16816(acc[1][nt2 * 2 + 0], Ah[ab][1], Bh[bb][0], Bh[bb][1]);
                mma16816(acc[1][nt2 * 2 + 1], Ah[ab][1], Bh[bb][2], Bh[bb][3]);
            }
            // stage consumed: free it for producers
            MBAR_ARRIVE(sb + SM_MBAR + 16 + (t & 1) * 8);

            // ---- epilogue (no CTA barrier — overlaps other warps' k-loops) ----
            if (job != 2 && jt > it) {
                // strictly upper triangular: row + column sums, no diag mask
                #pragma unroll
                for (int nt = 0; nt < 8; ++nt) {
                    float c0 = 0.f, c1 = 0.f;
                    #pragma unroll
                    for (int mt = 0; mt < 2; ++mt) {
                        #pragma unroll
                        for (int rh = 0; rh < 2; ++rh) {
                            const float e0 = fexp_b(acc[mt][nt][rh * 2 + 0]);
                            const float e1 = fexp_b(acc[mt][nt][rh * 2 + 1]);
                            rs[mt][rh] += e0 + e1;
                            c0 += e0; c1 += e1;
                        }
                    }
                    // reduce over the 8 lanes sharing (lane & 3): bits 2..4
                    c0 += __shfl_xor_sync(0xFFFFFFFF, c0, 4);
                    c0 += __shfl_xor_sync(0xFFFFFFFF, c0, 8);
                    c0 += __shfl_xor_sync(0xFFFFFFFF, c0, 16);
                    c1 += __shfl_xor_sync(0xFFFFFFFF, c1, 4);
                    c1 += __shfl_xor_sync(0xFFFFFFFF, c1, 8);
                    c1 += __shfl_xor_sync(0xFFFFFFFF, c1, 16);
                    if (lane < 4) {
                        const int lc = t * 128 + wcol * 64 + nt * 8 + lane * 2;
                        atomicAdd(&scol[lc], c0);
                        atomicAdd(&scol[lc + 1], c1);
                    }
                }
            } else {
                // row-only path (at job, or diagonal tiles of symmetric jobs)
                const bool dt = (jt == it);
                #pragma unroll
                for (int nt = 0; nt < 8; ++nt) {
                    #pragma unroll
                    for (int mt = 0; mt < 2; ++mt) {
                        #pragma unroll
                        for (int rh = 0; rh < 2; ++rh) {
                            float v0 = acc[mt][nt][rh * 2 + 0];
                            float v1 = acc[mt][nt][rh * 2 + 1];
                            if (dt) {
                                const int gr = i0 + wrow * 32 + mt * 16 + rh * 8 + (lane >> 2);
                                const int gc0 = j0 + wcol * 64 + nt * 8 + (lane & 3) * 2;
                                if (gr == gc0) v0 = -1e30f;
                                if (gr == gc0 + 1) v1 = -1e30f;
                            }
                            rs[mt][rh] += fexp_b(v0) + fexp_b(v1);
                        }
                    }
                }
            }
        } else {
            // discarded tile (jt < it on symmetric jobs): no compute,
            // but still recycle the stage for the producer side.
            MBAR_ARRIVE(sb + SM_MBAR + 16 + (t & 1) * 8);
        }
    }

    // ---- row flush: quad reduce + global atomics ----
    float* dst = (job == 2) ? g_neg : g_pos;
    #pragma unroll
    for (int mt = 0; mt < 2; ++mt) {
        #pragma unroll
        for (int rh = 0; rh < 2; ++rh) {
            float s = rs[mt][rh];
            s += __shfl_xor_sync(0xFFFFFFFF, s, 1);
            s += __shfl_xor_sync(0xFFFFFFFF, s, 2);
            if ((lane & 3) == 0) {
                const int gr = i0 + wrow * 32 + mt * 16 + rh * 8 + (lane >> 2);
                atomicAdd(dst + gr, s);
            }
        }
    }

    // ---- column flush (symmetric jobs: transpose contribution) ----
    if (job != 2) {
        __syncthreads();
        #pragma unroll
        for (int q = 0; q < 4; ++q) {
            const int idx = tid + q * 256;
            const float v = scol[idx];
            if (v != 0.0f) atomicAdd(&g_pos[j0base + idx], v);
        }
    }
}

// ---------------- per-row reduction (+ fused finalize) ----------------
__global__ void esup_rowreduce_kernel(const float* __restrict__ z_au,
                                      const float* __restrict__ z_tp,
                                      const float* __restrict__ fc,
                                      float* __restrict__ out) {
    __shared__ float sv[8], sp[8];
    const int lane = threadIdx.x & 31;
    const int wid = threadIdx.x >> 5;
    const int row = blockIdx.x * 8 + wid;

    const float4 a = *(const float4*)(z_au + (size_t)row * DD + lane * 4);
    const float4 b = *(const float4*)(z_tp + (size_t)row * DD + lane * 4);
    const float4 w0 = *(const float4*)(fc + lane * 4);
    const float4 w1 = *(const float4*)(fc + DD + lane * 4);

    float diag = a.x * b.x + a.y * b.y + a.z * b.z + a.w * b.w;
    float pt = (a.x - b.x) * (w1.x - w0.x) + (a.y - b.y) * (w1.y - w0.y) +
               (a.z - b.z) * (w1.z - w0.z) + (a.w - b.w) * (w1.w - w0.w);
    #pragma unroll
    for (int s = 16; s > 0; s >>= 1) {
        diag += __shfl_xor_sync(0xFFFFFFFF, diag, s);
        pt   += __shfl_xor_sync(0xFFFFFFFF, pt, s);
    }
    if (lane == 0) {
        const float pos = EXPBIAS + logf(g_pos[row]);
        const float neg = EXPBIAS + logf(g_neg[row]);
        sv[wid] = -pos + neg + ALPHA * diag;
        sp[wid] = pt;
    }
    __syncthreads();
    if (threadIdx.x == 0) {
        double s = 0.0, p = 0.0;
        #pragma unroll
        for (int i = 0; i < 8; ++i) { s += (double)sv[i]; p += (double)sp[i]; }
        atomicAdd(&g_supcon, s);
        atomicAdd(&g_pt, p);
        __threadfence();
        const unsigned prev = atomicAdd(&g_done, 1u);
        if (prev == gridDim.x - 1) {
            const double st = atomicAdd(&g_supcon, 0.0);
            const double pp = atomicAdd(&g_pt, 0.0);
            out[0] = (float)((pp / (double)NR + st) / (double)(NR + 2));
        }
    }
}

// ---------------- launch ----------------
extern "C" void kernel_launch(void* const* d_in, const int* in_sizes, int n_in,
                              void* d_out, int out_size) {
    const float* z_au = (const float*)d_in[0];
    const float* z_tp = (const float*)d_in[1];
    const float* fc   = (const float*)d_in[2];
    float* out = (float*)d_out;

    cudaFuncSetAttribute(esup_mma_kernel,
                         cudaFuncAttributeMaxDynamicSharedMemorySize, SMEM_BYTES);

    esup_split_kernel<<<(NR * DD / 4) / 256, 256>>>(z_au, z_tp);
    esup_mma_kernel<<<1088, 256, SMEM_BYTES>>>();
    esup_rowreduce_kernel<<<NR / 8, 256>>>(z_au, z_tp, fc, out);
}